// round 1
// baseline (speedup 1.0000x reference)
#include <cuda_runtime.h>
#include <math.h>
#include <stdint.h>

#define Nn 4096
#define Mm 4096
#define Dd 64
#define LAMDA 0.01f
#define STOP_THR 1e-7
#define MAX_ITER 100
#define NB 128
#define NT 256

// ---------------- device globals (no cudaMalloc allowed) ----------------
__device__ float  g_K[(size_t)Nn * Mm];   // 64 MB kernel matrix
__device__ float  g_a[2][Nn];
__device__ float  g_b[2][Mm];
__device__ double g_disp[Nn];
__device__ double g_rowcost[Nn];
__device__ int    g_done;
__device__ int    g_final;     // parity of the final a/b buffers
__device__ unsigned g_bar_cnt; // grid barrier counter

// ---------------- init ----------------
__global__ void init_kernel() {
    int t = threadIdx.x;
    for (int i = t; i < Nn; i += blockDim.x) {
        g_a[0][i] = 1.0f / (float)Nn;  // a0 = mu.sum()/n normalized = 1/n
        g_b[0][i] = 1.0f;              // b0 = ones
    }
    if (t == 0) {
        g_done = 0;
        g_final = 0;       // parity after 100 iters is 0 if never converged
        g_bar_cnt = 0;
    }
}

// ---------------- C and K builder ----------------
// C = |x|^2 + |y|^2 - 2 x y^T ; K = exp(-LAMDA*C). C written straight into d_out.
__global__ void __launch_bounds__(256) ck_kernel(const float* __restrict__ x,
                                                 const float* __restrict__ y,
                                                 float* __restrict__ Cout) {
    __shared__ float xs[64][65];
    __shared__ float ys[64][65];
    __shared__ float xn[64], yn[64];
    const int i0 = blockIdx.y * 64, j0 = blockIdx.x * 64;

    for (int idx = threadIdx.x; idx < 64 * 64; idx += 256) {
        int r = idx >> 6, c = idx & 63;
        xs[r][c] = x[(size_t)(i0 + r) * Dd + c];
        ys[r][c] = y[(size_t)(j0 + r) * Dd + c];
    }
    __syncthreads();
    if (threadIdx.x < 64) {
        int r = threadIdx.x;
        float s = 0.f;
        #pragma unroll
        for (int k = 0; k < 64; k++) s += xs[r][k] * xs[r][k];
        xn[r] = s;
    } else if (threadIdx.x < 128) {
        int r = threadIdx.x - 64;
        float s = 0.f;
        #pragma unroll
        for (int k = 0; k < 64; k++) s += ys[r][k] * ys[r][k];
        yn[r] = s;
    }
    __syncthreads();

    const int tx = threadIdx.x & 15, ty = threadIdx.x >> 4;
    float acc[4][4] = {};
    for (int k = 0; k < 64; k++) {
        float xv[4], yv[4];
        #pragma unroll
        for (int u = 0; u < 4; u++) xv[u] = xs[ty * 4 + u][k];
        #pragma unroll
        for (int v = 0; v < 4; v++) yv[v] = ys[tx * 4 + v][k];
        #pragma unroll
        for (int u = 0; u < 4; u++)
            #pragma unroll
            for (int v = 0; v < 4; v++) acc[u][v] += xv[u] * yv[v];
    }
    #pragma unroll
    for (int u = 0; u < 4; u++) {
        #pragma unroll
        for (int v = 0; v < 4; v++) {
            int i = i0 + ty * 4 + u, j = j0 + tx * 4 + v;
            float Cv = xn[ty * 4 + u] + yn[tx * 4 + v] - 2.0f * acc[u][v];
            size_t off = (size_t)i * Mm + j;
            Cout[off] = Cv;
            g_K[off] = expf(-LAMDA * Cv);
        }
    }
}

// ---------------- persistent Sinkhorn kernel ----------------
__device__ __forceinline__ void gbar(unsigned gen) {
    __syncthreads();
    if (threadIdx.x == 0) {
        __threadfence();
        atomicAdd(&g_bar_cnt, 1u);
        volatile unsigned* p = &g_bar_cnt;
        while (*p < gen * NB) { /* spin */ }
    }
    __syncthreads();
}

__global__ void __launch_bounds__(NT) sink_kernel(const float* __restrict__ mu,
                                                  const float* __restrict__ nu,
                                                  float* __restrict__ out) {
    __shared__ float  sA[Mm];        // 16 KB (a_cur in phase A; b_new in phase B; b_fin at end)
    __shared__ float  sB[Mm];        // 16 KB (b_ent in phase B)
    __shared__ float  sred[8][33];
    __shared__ double sdred[NT];

    const int tid = threadIdx.x, blk = blockIdx.x;
    const int warp = tid >> 5, lane = tid & 31;
    unsigned gen = 0;

    for (int it = 0; it < MAX_ITER; ++it) {
        const int cur = it & 1, nxt = cur ^ 1;

        // ---- Phase A: b[nxt] = nu / (K^T a[cur]); block owns cols [blk*32, +32)
        for (int i = tid; i < Nn; i += NT) sA[i] = __ldcg(&g_a[cur][i]);
        __syncthreads();
        {
            const int j = blk * 32 + lane;
            const float* Kc = g_K + j;
            float a0 = 0.f, a1 = 0.f, a2 = 0.f, a3 = 0.f;
            for (int i = warp; i < Nn; i += 32) {
                a0 += Kc[(size_t)(i)      * Mm] * sA[i];
                a1 += Kc[(size_t)(i + 8)  * Mm] * sA[i + 8];
                a2 += Kc[(size_t)(i + 16) * Mm] * sA[i + 16];
                a3 += Kc[(size_t)(i + 24) * Mm] * sA[i + 24];
            }
            sred[warp][lane] = (a0 + a1) + (a2 + a3);
        }
        __syncthreads();
        if (warp == 0) {
            float s = 0.f;
            #pragma unroll
            for (int w = 0; w < 8; ++w) s += sred[w][lane];
            int j = blk * 32 + lane;
            g_b[nxt][j] = __ldg(&nu[j]) / s;
        }
        gbar(++gen);

        // ---- Phase B: t = K b_new (+ fused S-GEMVs for disp); block owns rows [blk*32,+32)
        for (int i = tid; i < Mm; i += NT) sA[i] = __ldcg(&g_b[nxt][i]);
        for (int i = tid; i < Mm; i += NT) sB[i] = __ldcg(&g_b[cur][i]);
        __syncthreads();
        #pragma unroll
        for (int rr = 0; rr < 4; ++rr) {
            const int i = blk * 32 + warp * 4 + rr;
            const float* Kr = g_K + (size_t)i * Mm;
            float t = 0.f, s1 = 0.f, s2 = 0.f, s3 = 0.f;
            #pragma unroll 4
            for (int j = lane; j < Mm; j += 32) {
                float k  = Kr[j];
                float bn = sA[j], be = sB[j];
                float k2 = k * k;
                t  += k  * bn;
                s1 += k2 * bn * bn;
                s2 += k2 * bn * be;
                s3 += k2 * be * be;
            }
            #pragma unroll
            for (int off = 16; off; off >>= 1) {
                t  += __shfl_down_sync(0xffffffffu, t,  off);
                s1 += __shfl_down_sync(0xffffffffu, s1, off);
                s2 += __shfl_down_sync(0xffffffffu, s2, off);
                s3 += __shfl_down_sync(0xffffffffu, s3, off);
            }
            if (lane == 0) {
                float an = __ldg(&mu[i]) / t;
                g_a[nxt][i] = an;
                double dan = (double)an;
                double dao = (double)__ldcg(&g_a[cur][i]);
                double d = (it == 0)
                    ? dan * dan * (double)s1
                    : dan * dan * (double)s1 - 2.0 * dan * dao * (double)s2
                      + dao * dao * (double)s3;
                g_disp[i] = d;
            }
        }
        gbar(++gen);

        // ---- convergence check (deterministic fp64 tree in block 0)
        if (blk == 0) {
            double s = 0.0;
            for (int i = tid; i < Nn; i += NT) s += __ldcg(&g_disp[i]);
            sdred[tid] = s;
            __syncthreads();
            for (int off = NT / 2; off; off >>= 1) {
                if (tid < off) sdred[tid] += sdred[tid + off];
                __syncthreads();
            }
            if (tid == 0 && sdred[0] <= STOP_THR) {
                g_final = nxt;
                g_done = 1;
            }
        }
        gbar(++gen);
        if (*(volatile int*)&g_done) break;
    }

    // ---- epilogue: P = a*K*b^T, cost = sum(P*C)
    const int fpar = *(volatile int*)&g_final;
    for (int i = tid; i < Mm; i += NT) sA[i] = __ldcg(&g_b[fpar][i]);
    __syncthreads();

    float* Pout = out + 1;
    const float* Cmat = out + 1 + (size_t)Nn * Mm;
    #pragma unroll
    for (int rr = 0; rr < 4; ++rr) {
        const int i = blk * 32 + warp * 4 + rr;
        const float ai = __ldcg(&g_a[fpar][i]);
        const float* Kr = g_K + (size_t)i * Mm;
        const float* Cr = Cmat + (size_t)i * Mm;
        float* Pr = Pout + (size_t)i * Mm;
        double cs = 0.0;
        #pragma unroll 4
        for (int j = lane; j < Mm; j += 32) {
            float p = ai * Kr[j] * sA[j];
            Pr[j] = p;
            cs += (double)p * (double)Cr[j];
        }
        #pragma unroll
        for (int off = 16; off; off >>= 1)
            cs += __shfl_down_sync(0xffffffffu, cs, off);
        if (lane == 0) g_rowcost[i] = cs;
    }
    gbar(++gen);
    if (blk == 0) {
        double s = 0.0;
        for (int i = tid; i < Nn; i += NT) s += __ldcg(&g_rowcost[i]);
        sdred[tid] = s;
        __syncthreads();
        for (int off = NT / 2; off; off >>= 1) {
            if (tid < off) sdred[tid] += sdred[tid + off];
            __syncthreads();
        }
        if (tid == 0) out[0] = (float)sdred[0];
    }
}

// ---------------- launch ----------------
extern "C" void kernel_launch(void* const* d_in, const int* in_sizes, int n_in,
                              void* d_out, int out_size) {
    const float* x  = (const float*)d_in[0];   // [4096,64]
    const float* y  = (const float*)d_in[1];   // [4096,64]
    const float* mu = (const float*)d_in[2];   // [4096]
    const float* nu = (const float*)d_in[3];   // [4096]
    float* out = (float*)d_out;                // [1 + N*M + N*M] = cost | P | C

    float* Cout = out + 1 + (size_t)Nn * Mm;

    init_kernel<<<1, 256>>>();
    ck_kernel<<<dim3(Mm / 64, Nn / 64), 256>>>(x, y, Cout);
    sink_kernel<<<NB, NT>>>(mu, nu, out);
}

// round 2
// speedup vs baseline: 1.0032x; 1.0032x over previous
#include <cuda_runtime.h>
#include <math.h>
#include <stdint.h>

#define Nn 4096
#define Mm 4096
#define Dd 64
#define LAMDA 0.01f
#define STOP_THR 1e-7
#define MAX_ITER 100
#define NB 128
#define NT 256

// ---------------- device globals (no cudaMalloc allowed) ----------------
__device__ float  g_K[(size_t)Nn * Mm];   // 64 MB kernel matrix
__device__ float  g_a[2][Nn];
__device__ float  g_b[2][Mm];
__device__ double g_disp[Nn];
__device__ double g_rowcost[Nn];
__device__ int    g_done;
__device__ int    g_final;     // parity of the final a/b buffers
__device__ unsigned g_bar_cnt; // grid barrier counter

// ---------------- init ----------------
__global__ void init_kernel() {
    int t = threadIdx.x;
    for (int i = t; i < Nn; i += blockDim.x) {
        g_a[0][i] = 1.0f / (float)Nn;  // a0 = mu.sum()/n normalized = 1/n
        g_b[0][i] = 1.0f;              // b0 = ones
    }
    if (t == 0) {
        g_done = 0;
        g_final = 0;       // parity after 100 iters is 0 if never converged
        g_bar_cnt = 0;
    }
}

// ---------------- C and K builder ----------------
// C = |x|^2 + |y|^2 - 2 x y^T ; K = exp(-LAMDA*C). C written straight into d_out.
__global__ void __launch_bounds__(256) ck_kernel(const float* __restrict__ x,
                                                 const float* __restrict__ y,
                                                 float* __restrict__ Cout) {
    __shared__ float xs[64][65];
    __shared__ float ys[64][65];
    __shared__ float xn[64], yn[64];
    const int i0 = blockIdx.y * 64, j0 = blockIdx.x * 64;

    for (int idx = threadIdx.x; idx < 64 * 64; idx += 256) {
        int r = idx >> 6, c = idx & 63;
        xs[r][c] = x[(size_t)(i0 + r) * Dd + c];
        ys[r][c] = y[(size_t)(j0 + r) * Dd + c];
    }
    __syncthreads();
    if (threadIdx.x < 64) {
        int r = threadIdx.x;
        float s = 0.f;
        #pragma unroll
        for (int k = 0; k < 64; k++) s += xs[r][k] * xs[r][k];
        xn[r] = s;
    } else if (threadIdx.x < 128) {
        int r = threadIdx.x - 64;
        float s = 0.f;
        #pragma unroll
        for (int k = 0; k < 64; k++) s += ys[r][k] * ys[r][k];
        yn[r] = s;
    }
    __syncthreads();

    const int tx = threadIdx.x & 15, ty = threadIdx.x >> 4;
    float acc[4][4] = {};
    for (int k = 0; k < 64; k++) {
        float xv[4], yv[4];
        #pragma unroll
        for (int u = 0; u < 4; u++) xv[u] = xs[ty * 4 + u][k];
        #pragma unroll
        for (int v = 0; v < 4; v++) yv[v] = ys[tx * 4 + v][k];
        #pragma unroll
        for (int u = 0; u < 4; u++)
            #pragma unroll
            for (int v = 0; v < 4; v++) acc[u][v] += xv[u] * yv[v];
    }
    #pragma unroll
    for (int u = 0; u < 4; u++) {
        #pragma unroll
        for (int v = 0; v < 4; v++) {
            int i = i0 + ty * 4 + u, j = j0 + tx * 4 + v;
            float Cv = xn[ty * 4 + u] + yn[tx * 4 + v] - 2.0f * acc[u][v];
            size_t off = (size_t)i * Mm + j;
            Cout[off] = Cv;
            g_K[off] = expf(-LAMDA * Cv);
        }
    }
}

// ---------------- persistent Sinkhorn kernel ----------------
__device__ __forceinline__ void gbar(unsigned gen) {
    __syncthreads();
    if (threadIdx.x == 0) {
        __threadfence();
        atomicAdd(&g_bar_cnt, 1u);
        volatile unsigned* p = &g_bar_cnt;
        while (*p < gen * NB) { /* spin */ }
    }
    __syncthreads();
}

__global__ void __launch_bounds__(NT) sink_kernel(const float* __restrict__ mu,
                                                  const float* __restrict__ nu,
                                                  float* __restrict__ out) {
    __shared__ float  sA[Mm];        // 16 KB (a_cur in phase A; b_new in phase B; b_fin at end)
    __shared__ float  sB[Mm];        // 16 KB (b_ent in phase B)
    __shared__ float  sred[8][33];
    __shared__ double sdred[NT];

    const int tid = threadIdx.x, blk = blockIdx.x;
    const int warp = tid >> 5, lane = tid & 31;
    unsigned gen = 0;

    for (int it = 0; it < MAX_ITER; ++it) {
        const int cur = it & 1, nxt = cur ^ 1;

        // ---- Phase A: b[nxt] = nu / (K^T a[cur]); block owns cols [blk*32, +32)
        for (int i = tid; i < Nn; i += NT) sA[i] = __ldcg(&g_a[cur][i]);
        __syncthreads();
        {
            const int j = blk * 32 + lane;
            const float* Kc = g_K + j;
            float a0 = 0.f, a1 = 0.f, a2 = 0.f, a3 = 0.f;
            for (int i = warp; i < Nn; i += 32) {
                a0 += Kc[(size_t)(i)      * Mm] * sA[i];
                a1 += Kc[(size_t)(i + 8)  * Mm] * sA[i + 8];
                a2 += Kc[(size_t)(i + 16) * Mm] * sA[i + 16];
                a3 += Kc[(size_t)(i + 24) * Mm] * sA[i + 24];
            }
            sred[warp][lane] = (a0 + a1) + (a2 + a3);
        }
        __syncthreads();
        if (warp == 0) {
            float s = 0.f;
            #pragma unroll
            for (int w = 0; w < 8; ++w) s += sred[w][lane];
            int j = blk * 32 + lane;
            g_b[nxt][j] = __ldg(&nu[j]) / s;
        }
        gbar(++gen);

        // ---- Phase B: t = K b_new (+ fused S-GEMVs for disp); block owns rows [blk*32,+32)
        for (int i = tid; i < Mm; i += NT) sA[i] = __ldcg(&g_b[nxt][i]);
        for (int i = tid; i < Mm; i += NT) sB[i] = __ldcg(&g_b[cur][i]);
        __syncthreads();
        #pragma unroll
        for (int rr = 0; rr < 4; ++rr) {
            const int i = blk * 32 + warp * 4 + rr;
            const float* Kr = g_K + (size_t)i * Mm;
            float t = 0.f, s1 = 0.f, s2 = 0.f, s3 = 0.f;
            #pragma unroll 4
            for (int j = lane; j < Mm; j += 32) {
                float k  = Kr[j];
                float bn = sA[j], be = sB[j];
                float k2 = k * k;
                t  += k  * bn;
                s1 += k2 * bn * bn;
                s2 += k2 * bn * be;
                s3 += k2 * be * be;
            }
            #pragma unroll
            for (int off = 16; off; off >>= 1) {
                t  += __shfl_down_sync(0xffffffffu, t,  off);
                s1 += __shfl_down_sync(0xffffffffu, s1, off);
                s2 += __shfl_down_sync(0xffffffffu, s2, off);
                s3 += __shfl_down_sync(0xffffffffu, s3, off);
            }
            if (lane == 0) {
                float an = __ldg(&mu[i]) / t;
                g_a[nxt][i] = an;
                double dan = (double)an;
                double dao = (double)__ldcg(&g_a[cur][i]);
                double d = (it == 0)
                    ? dan * dan * (double)s1
                    : dan * dan * (double)s1 - 2.0 * dan * dao * (double)s2
                      + dao * dao * (double)s3;
                g_disp[i] = d;
            }
        }
        gbar(++gen);

        // ---- convergence check (deterministic fp64 tree in block 0)
        if (blk == 0) {
            double s = 0.0;
            for (int i = tid; i < Nn; i += NT) s += __ldcg(&g_disp[i]);
            sdred[tid] = s;
            __syncthreads();
            for (int off = NT / 2; off; off >>= 1) {
                if (tid < off) sdred[tid] += sdred[tid + off];
                __syncthreads();
            }
            if (tid == 0 && sdred[0] <= STOP_THR) {
                g_final = nxt;
                g_done = 1;
            }
        }
        gbar(++gen);
        if (*(volatile int*)&g_done) break;
    }

    // ---- epilogue: P = a*K*b^T, cost = sum(P*C)
    const int fpar = *(volatile int*)&g_final;
    for (int i = tid; i < Mm; i += NT) sA[i] = __ldcg(&g_b[fpar][i]);
    __syncthreads();

    float* Pout = out + 1;
    const float* Cmat = out + 1 + (size_t)Nn * Mm;
    #pragma unroll
    for (int rr = 0; rr < 4; ++rr) {
        const int i = blk * 32 + warp * 4 + rr;
        const float ai = __ldcg(&g_a[fpar][i]);
        const float* Kr = g_K + (size_t)i * Mm;
        const float* Cr = Cmat + (size_t)i * Mm;
        float* Pr = Pout + (size_t)i * Mm;
        double cs = 0.0;
        #pragma unroll 4
        for (int j = lane; j < Mm; j += 32) {
            float p = ai * Kr[j] * sA[j];
            Pr[j] = p;
            cs += (double)p * (double)Cr[j];
        }
        #pragma unroll
        for (int off = 16; off; off >>= 1)
            cs += __shfl_down_sync(0xffffffffu, cs, off);
        if (lane == 0) g_rowcost[i] = cs;
    }
    gbar(++gen);
    if (blk == 0) {
        double s = 0.0;
        for (int i = tid; i < Nn; i += NT) s += __ldcg(&g_rowcost[i]);
        sdred[tid] = s;
        __syncthreads();
        for (int off = NT / 2; off; off >>= 1) {
            if (tid < off) sdred[tid] += sdred[tid + off];
            __syncthreads();
        }
        if (tid == 0) out[0] = (float)sdred[0];
    }
}

// ---------------- launch ----------------
extern "C" void kernel_launch(void* const* d_in, const int* in_sizes, int n_in,
                              void* d_out, int out_size) {
    const float* x  = (const float*)d_in[0];   // [4096,64]
    const float* y  = (const float*)d_in[1];   // [4096,64]
    const float* mu = (const float*)d_in[2];   // [4096]
    const float* nu = (const float*)d_in[3];   // [4096]
    float* out = (float*)d_out;                // [1 + N*M + N*M] = cost | P | C

    float* Cout = out + 1 + (size_t)Nn * Mm;

    init_kernel<<<1, 256>>>();
    ck_kernel<<<dim3(Mm / 64, Nn / 64), 256>>>(x, y, Cout);
    sink_kernel<<<NB, NT>>>(mu, nu, out);
}

// round 3
// speedup vs baseline: 1.2806x; 1.2766x over previous
#include <cuda_runtime.h>
#include <math.h>
#include <stdint.h>

#define Nn 4096
#define Mm 4096
#define LAMDA 0.01f
#define STOP_THR 1e-7
#define MAX_ITER 100
#define NB 128
#define NT 256
#define S2 70   // smem row stride (floats), even, gcd-friendly for banks

typedef unsigned long long ull;

// ---------------- device globals (no cudaMalloc allowed) ----------------
__device__ float  g_K[(size_t)Nn * Mm];   // 64 MB kernel matrix
__device__ float  g_a[2][Nn];
__device__ float  g_b[2][Mm];
__device__ double g_bdisp[NB];
__device__ double g_bcost[NB];
__device__ unsigned g_bar_cnt;

// ---------------- fast exp: FFMA-only (no MUFU) ----------------
// valid for |x| < ~80; here x in [-4, ~0]. rel err ~1e-7.
__device__ __forceinline__ float fexp(float xx) {
    float t  = fmaf(xx, 1.4426950408889634f, 12582912.0f); // round(x*log2e) via magic
    int   n  = __float_as_int(t) - 0x4B400000;
    float fn = t - 12582912.0f;
    float r  = fmaf(fn, -0.693145751953125f, xx);          // Cody-Waite hi
    r        = fmaf(fn, -1.42860677e-6f, r);               // Cody-Waite lo
    float p  = 1.3888890e-3f;
    p = fmaf(p, r, 8.3333338e-3f);
    p = fmaf(p, r, 4.1666668e-2f);
    p = fmaf(p, r, 1.6666667e-1f);
    p = fmaf(p, r, 5.0000000e-1f);
    p = fmaf(p, r, 1.0f);
    p = fmaf(p, r, 1.0f);
    return __int_as_float(__float_as_int(p) + (n << 23));
}

#define FMA2(d, a, b) \
    asm("fma.rn.f32x2 %0, %1, %2, %0;" : "+l"(d) : "l"(a), "l"(b))
#define UNPACK2(lo, hi, v) \
    asm("mov.b64 {%0, %1}, %2;" : "=f"(lo), "=f"(hi) : "l"(v))

// ---------------- init ----------------
__global__ void init_kernel() {
    int t = threadIdx.x;
    for (int i = t; i < Nn; i += blockDim.x) {
        g_a[0][i] = 1.0f / (float)Nn;  // a0 = 1/n
        g_b[0][i] = 1.0f;              // b0 = ones
    }
    if (t == 0) g_bar_cnt = 0;
}

// ---------------- C and K builder ----------------
// Tile 128(i) x 64(j), 256 threads, 8x4 per thread, FFMA2 with k-paired accs.
__global__ void __launch_bounds__(256) ck_kernel(const float* __restrict__ x,
                                                 const float* __restrict__ y,
                                                 float* __restrict__ Cout) {
    extern __shared__ float sm[];
    float* XS = sm;                 // [128][S2]
    float* YS = sm + 128 * S2;      // [64][S2]
    float* xn = YS + 64 * S2;       // [128]
    float* yn = xn + 128;           // [64]

    const int tid = threadIdx.x;
    const int i0 = blockIdx.y * 128, j0 = blockIdx.x * 64;

    // row-major copy with float2 (lanes: consecutive c within a row)
    for (int t = tid; t < 4096; t += 256) {
        int r = t >> 5, c = t & 31;
        float2 v = __ldg((const float2*)(x + (size_t)(i0 + r) * 64) + c);
        *(float2*)(XS + r * S2 + 2 * c) = v;
    }
    for (int t = tid; t < 2048; t += 256) {
        int r = t >> 5, c = t & 31;
        float2 v = __ldg((const float2*)(y + (size_t)(j0 + r) * 64) + c);
        *(float2*)(YS + r * S2 + 2 * c) = v;
    }
    __syncthreads();

    // norms
    if (tid < 128) {
        float s = 0.f;
        #pragma unroll
        for (int k = 0; k < 64; k++) { float v = XS[tid * S2 + k]; s = fmaf(v, v, s); }
        xn[tid] = s;
    } else if (tid < 192) {
        int r = tid - 128;
        float s = 0.f;
        #pragma unroll
        for (int k = 0; k < 64; k++) { float v = YS[r * S2 + k]; s = fmaf(v, v, s); }
        yn[r] = s;
    }
    __syncthreads();

    const int tx = tid & 15, ty = tid >> 4;
    const int iy = ty * 8;

    ull acc[8][4];
    #pragma unroll
    for (int u = 0; u < 8; u++)
        #pragma unroll
        for (int w = 0; w < 4; w++) acc[u][w] = 0ULL;

    #pragma unroll 4
    for (int kp = 0; kp < 32; kp++) {
        const int k = kp * 2;
        ull xp[8], yp[4];
        #pragma unroll
        for (int u = 0; u < 8; u++)
            xp[u] = *(const ull*)(XS + (iy + u) * S2 + k);
        #pragma unroll
        for (int w = 0; w < 4; w++)
            yp[w] = *(const ull*)(YS + (tx + 16 * w) * S2 + k);
        #pragma unroll
        for (int u = 0; u < 8; u++)
            #pragma unroll
            for (int w = 0; w < 4; w++)
                FMA2(acc[u][w], xp[u], yp[w]);
    }

    #pragma unroll
    for (int u = 0; u < 8; u++) {
        const int i = i0 + iy + u;
        const float xni = xn[iy + u];
        #pragma unroll
        for (int w = 0; w < 4; w++) {
            const int jl = tx + 16 * w;
            float lo, hi;
            UNPACK2(lo, hi, acc[u][w]);
            float dot = lo + hi;
            float Cv = xni + yn[jl] - 2.0f * dot;
            size_t off = (size_t)i * Mm + j0 + jl;
            __stcs(Cout + off, Cv);          // streaming: C not needed until epilogue
            g_K[off] = fexp(-LAMDA * Cv);    // keep K L2-resident
        }
    }
}

// ---------------- grid barrier ----------------
__device__ __forceinline__ void gbar(unsigned gen) {
    __syncthreads();
    if (threadIdx.x == 0) {
        __threadfence();
        atomicAdd(&g_bar_cnt, 1u);
        volatile unsigned* p = &g_bar_cnt;
        while (*p < gen * NB) { /* spin */ }
    }
    __syncthreads();
}

// ---------------- persistent Sinkhorn kernel ----------------
__global__ void __launch_bounds__(NT) sink_kernel(const float* __restrict__ mu,
                                                  const float* __restrict__ nu,
                                                  float* __restrict__ out) {
    __shared__ float  sA[Nn];
    __shared__ float  sB[Mm];
    __shared__ float  sred[8][33];
    __shared__ double sdd[NT];

    const int tid = threadIdx.x, blk = blockIdx.x;
    const int warp = tid >> 5, lane = tid & 31;
    unsigned gen = 0;
    int fpar = 0;

    for (int it = 0; it < MAX_ITER; ++it) {
        const int cur = it & 1, nxt = cur ^ 1;

        // ---- Phase A: b[nxt] = nu / (K^T a[cur]); block owns cols [blk*32, +32)
        for (int i = tid; i < Nn; i += NT) sA[i] = __ldcg(&g_a[cur][i]);
        __syncthreads();
        {
            const int j = blk * 32 + lane;
            const float* Kc = g_K + j;
            float a0 = 0.f, a1 = 0.f, a2 = 0.f, a3 = 0.f;
            for (int i = warp; i < Nn; i += 32) {
                a0 = fmaf(Kc[(size_t)(i)      * Mm], sA[i],      a0);
                a1 = fmaf(Kc[(size_t)(i + 8)  * Mm], sA[i + 8],  a1);
                a2 = fmaf(Kc[(size_t)(i + 16) * Mm], sA[i + 16], a2);
                a3 = fmaf(Kc[(size_t)(i + 24) * Mm], sA[i + 24], a3);
            }
            sred[warp][lane] = (a0 + a1) + (a2 + a3);
        }
        __syncthreads();
        if (warp == 0) {
            float s = 0.f;
            #pragma unroll
            for (int w = 0; w < 8; ++w) s += sred[w][lane];
            int j = blk * 32 + lane;
            g_b[nxt][j] = __ldg(&nu[j]) / s;
        }
        gbar(++gen);

        // ---- Phase B: a[nxt] = mu / (K b_new) + fused disp partials
        for (int i = tid; i < Mm; i += NT) sA[i] = __ldcg(&g_b[nxt][i]);
        for (int i = tid; i < Mm; i += NT) sB[i] = __ldcg(&g_b[cur][i]);
        __syncthreads();
        #pragma unroll
        for (int rr = 0; rr < 4; ++rr) {
            const int i = blk * 32 + warp * 4 + rr;
            const float* Kr = g_K + (size_t)i * Mm;
            float t = 0.f, s1 = 0.f, s2 = 0.f, s3 = 0.f;
            #pragma unroll 4
            for (int j = lane; j < Mm; j += 32) {
                float k  = Kr[j];
                float bn = sA[j], be = sB[j];
                float k2 = k * k;
                t  = fmaf(k,       bn, t);
                s1 = fmaf(k2 * bn, bn, s1);
                s2 = fmaf(k2 * bn, be, s2);
                s3 = fmaf(k2 * be, be, s3);
            }
            #pragma unroll
            for (int off = 16; off; off >>= 1) {
                t  += __shfl_down_sync(0xffffffffu, t,  off);
                s1 += __shfl_down_sync(0xffffffffu, s1, off);
                s2 += __shfl_down_sync(0xffffffffu, s2, off);
                s3 += __shfl_down_sync(0xffffffffu, s3, off);
            }
            if (lane == 0) {
                float an = __ldg(&mu[i]) / t;
                g_a[nxt][i] = an;
                double dan = (double)an;
                double dao = (double)__ldcg(&g_a[cur][i]);
                double d = (it == 0)
                    ? dan * dan * (double)s1
                    : dan * dan * (double)s1 - 2.0 * dan * dao * (double)s2
                      + dao * dao * (double)s3;
                sdd[warp * 4 + rr] = d;
            }
        }
        __syncthreads();
        if (tid == 0) {
            double s = 0.0;
            #pragma unroll
            for (int q = 0; q < 32; ++q) s += sdd[q];
            g_bdisp[blk] = s;
        }
        gbar(++gen);

        // ---- uniform convergence decision: every block reduces identically
        sdd[tid] = (tid < NB) ? __ldcg(&g_bdisp[tid]) : 0.0;
        __syncthreads();
        for (int off = NT / 2; off; off >>= 1) {
            if (tid < off) sdd[tid] += sdd[tid + off];
            __syncthreads();
        }
        double disp = sdd[0];
        __syncthreads();
        fpar = nxt;
        if (disp <= STOP_THR) break;
    }

    // ---- epilogue: P = a*K*b^T, cost = sum(P*C)
    __syncthreads();
    for (int i = tid; i < Mm; i += NT) sA[i] = __ldcg(&g_b[fpar][i]);
    __syncthreads();

    float* Pout = out + 1;
    const float* Cmat = out + 1 + (size_t)Nn * Mm;
    #pragma unroll
    for (int rr = 0; rr < 4; ++rr) {
        const int i = blk * 32 + warp * 4 + rr;
        const float ai = __ldcg(&g_a[fpar][i]);
        const float* Kr = g_K + (size_t)i * Mm;
        const float* Cr = Cmat + (size_t)i * Mm;
        float* Pr = Pout + (size_t)i * Mm;
        double cs = 0.0;
        #pragma unroll 4
        for (int j = lane; j < Mm; j += 32) {
            float p = ai * Kr[j] * sA[j];
            __stcs(&Pr[j], p);
            cs = fma((double)p, (double)__ldcs(&Cr[j]), cs);
        }
        #pragma unroll
        for (int off = 16; off; off >>= 1)
            cs += __shfl_down_sync(0xffffffffu, cs, off);
        if (lane == 0) sdd[warp * 4 + rr] = cs;
    }
    __syncthreads();
    if (tid == 0) {
        double s = 0.0;
        #pragma unroll
        for (int q = 0; q < 32; ++q) s += sdd[q];
        g_bcost[blk] = s;
    }
    gbar(++gen);
    if (blk == 0) {
        sdd[tid] = (tid < NB) ? __ldcg(&g_bcost[tid]) : 0.0;
        __syncthreads();
        for (int off = NT / 2; off; off >>= 1) {
            if (tid < off) sdd[tid] += sdd[tid + off];
            __syncthreads();
        }
        if (tid == 0) out[0] = (float)sdd[0];
    }
}

// ---------------- launch ----------------
extern "C" void kernel_launch(void* const* d_in, const int* in_sizes, int n_in,
                              void* d_out, int out_size) {
    const float* x  = (const float*)d_in[0];   // [4096,64]
    const float* y  = (const float*)d_in[1];   // [4096,64]
    const float* mu = (const float*)d_in[2];   // [4096]
    const float* nu = (const float*)d_in[3];   // [4096]
    float* out = (float*)d_out;                // [1 + N*M + N*M] = cost | P | C

    float* Cout = out + 1 + (size_t)Nn * Mm;

    const int ck_smem = (128 * S2 + 64 * S2 + 128 + 64) * (int)sizeof(float);
    cudaFuncSetAttribute(ck_kernel, cudaFuncAttributeMaxDynamicSharedMemorySize, ck_smem);

    init_kernel<<<1, 256>>>();
    ck_kernel<<<dim3(Mm / 64, Nn / 128), 256, ck_smem>>>(x, y, Cout);
    sink_kernel<<<NB, NT>>>(mu, nu, out);
}

// round 4
// speedup vs baseline: 1.5216x; 1.1882x over previous
#include <cuda_runtime.h>
#include <math.h>
#include <stdint.h>

#define Nn 4096
#define Mm 4096
#define LAMDA 0.01f
#define STOP_THR 1e-7
#define MAX_ITER 100
#define NB 128
#define NT 256
#define S2 70   // smem row stride (floats)

typedef unsigned long long ull;

// ---------------- device globals (no cudaMalloc allowed) ----------------
__device__ float  g_K[(size_t)Nn * Mm];   // 64 MB kernel matrix
__device__ float  g_a[2][Nn];
__device__ float  g_b[2][Mm];
__device__ double g_bdisp[NB];
__device__ double g_bcost[NB];
__device__ unsigned g_bar_cnt;            // monotonic arrive counter (never reset)

// ---------------- fast exp: FFMA-only (no MUFU), rel err ~1e-7 ----------
__device__ __forceinline__ float fexp(float xx) {
    float t  = fmaf(xx, 1.4426950408889634f, 12582912.0f);
    int   n  = __float_as_int(t) - 0x4B400000;
    float fn = t - 12582912.0f;
    float r  = fmaf(fn, -0.693145751953125f, xx);
    r        = fmaf(fn, -1.42860677e-6f, r);
    float p  = 1.3888890e-3f;
    p = fmaf(p, r, 8.3333338e-3f);
    p = fmaf(p, r, 4.1666668e-2f);
    p = fmaf(p, r, 1.6666667e-1f);
    p = fmaf(p, r, 5.0000000e-1f);
    p = fmaf(p, r, 1.0f);
    p = fmaf(p, r, 1.0f);
    return __int_as_float(__float_as_int(p) + (n << 23));
}

#define FMA2(d, a, b) \
    asm("fma.rn.f32x2 %0, %1, %2, %0;" : "+l"(d) : "l"(a), "l"(b))
#define MUL2(d, a, b) \
    asm("mul.rn.f32x2 %0, %1, %2;" : "=l"(d) : "l"(a), "l"(b))
#define UNPACK2(lo, hi, v) \
    asm("mov.b64 {%0, %1}, %2;" : "=f"(lo), "=f"(hi) : "l"(v))

// ------------- cheap acquire/release grid barrier (no MEMBAR.GPU) -------
__device__ __forceinline__ void red_rel_add1(unsigned* p) {
    asm volatile("red.release.gpu.global.add.u32 [%0], 1;" :: "l"(p) : "memory");
}
__device__ __forceinline__ unsigned ld_acq(unsigned* p) {
    unsigned v;
    asm volatile("ld.acquire.gpu.global.u32 %0, [%1];" : "=r"(v) : "l"(p) : "memory");
    return v;
}
__device__ __forceinline__ void gbar(unsigned target) {
    __syncthreads();
    if (threadIdx.x == 0) {
        red_rel_add1(&g_bar_cnt);
        while ((int)(ld_acq(&g_bar_cnt) - target) < 0) { }
    }
    __syncthreads();
}

// ---------------- fused persistent kernel ----------------
__global__ void __launch_bounds__(NT, 1)
fused_kernel(const float* __restrict__ x, const float* __restrict__ y,
             const float* __restrict__ mu, const float* __restrict__ nu,
             float* __restrict__ out) {
    extern __shared__ float sm[];
    __shared__ float  sred[8][33];
    __shared__ double sRow[32];
    __shared__ double sDS1[32];     // cached dan^2 * s1 per owned row
    __shared__ double sDisp;

    const int tid = threadIdx.x, blk = blockIdx.x;
    const int warp = tid >> 5, lane = tid & 31;
    const unsigned base = __ldcg(&g_bar_cnt);  // stable: no arrivals for ~50us
    unsigned gen = 0;

    float* Pout = out + 1;
    float* Cmat = out + 1 + (size_t)Nn * Mm;

    // init a/b slice (visible after first grid barrier)
    if (tid < 32) {
        g_a[0][blk * 32 + tid] = 1.0f / (float)Nn;
        g_b[0][blk * 32 + tid] = 1.0f;
    }

    // ================= CK phase: 16 tiles of 128x64 per block ============
    {
        float* XS = sm;                 // [128][S2]
        float* YS = sm + 128 * S2;      // [64][S2]
        float* xn = YS + 64 * S2;       // [128]
        float* yn = xn + 128;           // [64]
        const int i_tile = blk >> 2, jb = (blk & 3) * 16;
        const int i0 = i_tile * 128;

        for (int t = tid; t < 4096; t += NT) {
            int r = t >> 5, c = t & 31;
            float2 v = __ldg((const float2*)(x + (size_t)(i0 + r) * 64) + c);
            *(float2*)(XS + r * S2 + 2 * c) = v;
        }
        __syncthreads();
        if (tid < 128) {
            float s = 0.f;
            #pragma unroll
            for (int k = 0; k < 64; k++) { float v = XS[tid * S2 + k]; s = fmaf(v, v, s); }
            xn[tid] = s;
        }

        const int tx = tid & 15, ty = tid >> 4, iy = ty * 8;
        for (int s = 0; s < 16; s++) {
            const int j0 = (jb + s) * 64;
            __syncthreads();   // previous tile fully consumed
            for (int t = tid; t < 2048; t += NT) {
                int r = t >> 5, c = t & 31;
                float2 v = __ldg((const float2*)(y + (size_t)(j0 + r) * 64) + c);
                *(float2*)(YS + r * S2 + 2 * c) = v;
            }
            __syncthreads();
            if (tid < 64) {
                float sv = 0.f;
                #pragma unroll
                for (int k = 0; k < 64; k++) { float v = YS[tid * S2 + k]; sv = fmaf(v, v, sv); }
                yn[tid] = sv;
            }
            __syncthreads();

            ull acc[8][4];
            #pragma unroll
            for (int u = 0; u < 8; u++)
                #pragma unroll
                for (int w = 0; w < 4; w++) acc[u][w] = 0ULL;

            #pragma unroll 4
            for (int kp = 0; kp < 32; kp++) {
                const int k = kp * 2;
                ull xp[8], yp[4];
                #pragma unroll
                for (int u = 0; u < 8; u++)
                    xp[u] = *(const ull*)(XS + (iy + u) * S2 + k);
                #pragma unroll
                for (int w = 0; w < 4; w++)
                    yp[w] = *(const ull*)(YS + (tx + 16 * w) * S2 + k);
                #pragma unroll
                for (int u = 0; u < 8; u++)
                    #pragma unroll
                    for (int w = 0; w < 4; w++)
                        FMA2(acc[u][w], xp[u], yp[w]);
            }

            #pragma unroll
            for (int u = 0; u < 8; u++) {
                const int i = i0 + iy + u;
                const float xni = xn[iy + u];
                #pragma unroll
                for (int w = 0; w < 4; w++) {
                    const int jl = tx + 16 * w;
                    float lo, hi;
                    UNPACK2(lo, hi, acc[u][w]);
                    float Cv = xni + yn[jl] - 2.0f * (lo + hi);
                    size_t off = (size_t)i * Mm + j0 + jl;
                    __stcs(Cmat + off, Cv);
                    g_K[off] = fexp(-LAMDA * Cv);
                }
            }
        }
    }
    gbar(base + (++gen) * NB);

    // ================= Sinkhorn loop ======================================
    float* sA = sm;          // 16 KB
    float* sB = sm + Mm;     // 16 KB
    int fpar = 0;

    for (int it = 0; it < MAX_ITER; ++it) {
        const int cur = it & 1, nxt = cur ^ 1;

        // ---- Phase A: b[nxt] = nu / (K^T a[cur]); block owns cols [blk*32,+32)
        for (int i = tid; i < Nn; i += NT) sA[i] = __ldcg(&g_a[cur][i]);
        __syncthreads();
        {
            const int j = blk * 32 + lane;
            const float* Kc = g_K + j;
            float a0 = 0.f, a1 = 0.f, a2 = 0.f, a3 = 0.f;
            for (int i = warp; i < Nn; i += 32) {
                a0 = fmaf(Kc[(size_t)(i)      * Mm], sA[i],      a0);
                a1 = fmaf(Kc[(size_t)(i + 8)  * Mm], sA[i + 8],  a1);
                a2 = fmaf(Kc[(size_t)(i + 16) * Mm], sA[i + 16], a2);
                a3 = fmaf(Kc[(size_t)(i + 24) * Mm], sA[i + 24], a3);
            }
            sred[warp][lane] = (a0 + a1) + (a2 + a3);
        }
        __syncthreads();
        if (warp == 0) {
            float s = 0.f;
            #pragma unroll
            for (int w = 0; w < 8; ++w) s += sred[w][lane];
            int j = blk * 32 + lane;
            g_b[nxt][j] = __ldg(&nu[j]) / s;
        }
        gbar(base + (++gen) * NB);

        // ---- Phase B: a[nxt] = mu/(K b_new), fused f32x2 disp GEMVs
        for (int i = tid; i < Mm; i += NT) sA[i] = __ldcg(&g_b[nxt][i]);
        for (int i = tid; i < Mm; i += NT) sB[i] = __ldcg(&g_b[cur][i]);
        __syncthreads();
        #pragma unroll
        for (int rr = 0; rr < 4; ++rr) {
            const int i = blk * 32 + warp * 4 + rr;
            const ull* K2 = (const ull*)(g_K + (size_t)i * Mm);
            const ull* A2 = (const ull*)sA;
            const ull* B2 = (const ull*)sB;
            ull t = 0ULL, s1 = 0ULL, s2 = 0ULL;
            #pragma unroll 4
            for (int j = lane; j < Mm / 2; j += 32) {
                ull k = K2[j], bn = A2[j], be = B2[j];
                ull k2, tmp;
                MUL2(k2, k, k);
                FMA2(t, k, bn);
                MUL2(tmp, k2, bn);
                FMA2(s1, tmp, bn);
                FMA2(s2, tmp, be);
            }
            float tl, th, l1, h1, l2, h2;
            UNPACK2(tl, th, t);  UNPACK2(l1, h1, s1);  UNPACK2(l2, h2, s2);
            float tf = tl + th, s1f = l1 + h1, s2f = l2 + h2;
            #pragma unroll
            for (int off = 16; off; off >>= 1) {
                tf  += __shfl_down_sync(0xffffffffu, tf,  off);
                s1f += __shfl_down_sync(0xffffffffu, s1f, off);
                s2f += __shfl_down_sync(0xffffffffu, s2f, off);
            }
            if (lane == 0) {
                float an = __ldg(&mu[i]) / tf;
                g_a[nxt][i] = an;
                double dan = (double)an;
                double dao = (double)__ldcg(&g_a[cur][i]);
                double dS1 = dan * dan * (double)s1f;
                double d = (it == 0)
                    ? dS1
                    : dS1 - 2.0 * dan * dao * (double)s2f + sDS1[warp * 4 + rr];
                sDS1[warp * 4 + rr] = dS1;
                sRow[warp * 4 + rr] = d;
            }
        }
        __syncthreads();
        if (tid == 0) {
            double s = 0.0;
            #pragma unroll
            for (int q = 0; q < 32; ++q) s += sRow[q];
            g_bdisp[blk] = s;
        }
        gbar(base + (++gen) * NB);

        // ---- uniform convergence decision (warp 0 shuffle reduce)
        if (warp == 0) {
            double sd = __ldcg(&g_bdisp[lane])      + __ldcg(&g_bdisp[lane + 32])
                      + __ldcg(&g_bdisp[lane + 64]) + __ldcg(&g_bdisp[lane + 96]);
            #pragma unroll
            for (int off = 16; off; off >>= 1)
                sd += __shfl_down_sync(0xffffffffu, sd, off);
            if (lane == 0) sDisp = sd;
        }
        __syncthreads();
        fpar = nxt;
        if (sDisp <= STOP_THR) break;
    }

    // ================= epilogue: P = a*K*b^T, cost = sum(P*C) =============
    __syncthreads();
    for (int i = tid; i < Mm; i += NT) sA[i] = __ldcg(&g_b[fpar][i]);
    __syncthreads();

    #pragma unroll
    for (int rr = 0; rr < 4; ++rr) {
        const int i = blk * 32 + warp * 4 + rr;
        const float ai = __ldcg(&g_a[fpar][i]);
        const float* Kr = g_K + (size_t)i * Mm;
        const float* Cr = Cmat + (size_t)i * Mm;
        float* Pr = Pout + (size_t)i * Mm;
        double cs = 0.0;
        #pragma unroll 4
        for (int j = lane; j < Mm; j += 32) {
            float p = ai * Kr[j] * sA[j];
            __stcs(&Pr[j], p);
            cs = fma((double)p, (double)__ldcs(&Cr[j]), cs);
        }
        #pragma unroll
        for (int off = 16; off; off >>= 1)
            cs += __shfl_down_sync(0xffffffffu, cs, off);
        if (lane == 0) sRow[warp * 4 + rr] = cs;
    }
    __syncthreads();
    if (tid == 0) {
        double s = 0.0;
        #pragma unroll
        for (int q = 0; q < 32; ++q) s += sRow[q];
        g_bcost[blk] = s;
    }
    gbar(base + (++gen) * NB);
    if (blk == 0 && warp == 0) {
        double sc = __ldcg(&g_bcost[lane])      + __ldcg(&g_bcost[lane + 32])
                  + __ldcg(&g_bcost[lane + 64]) + __ldcg(&g_bcost[lane + 96]);
        #pragma unroll
        for (int off = 16; off; off >>= 1)
            sc += __shfl_down_sync(0xffffffffu, sc, off);
        if (lane == 0) out[0] = (float)sc;
    }
}

// ---------------- launch ----------------
extern "C" void kernel_launch(void* const* d_in, const int* in_sizes, int n_in,
                              void* d_out, int out_size) {
    const float* x  = (const float*)d_in[0];   // [4096,64]
    const float* y  = (const float*)d_in[1];   // [4096,64]
    const float* mu = (const float*)d_in[2];   // [4096]
    const float* nu = (const float*)d_in[3];   // [4096]
    float* out = (float*)d_out;                // [1 + N*M + N*M] = cost | P | C

    const int smem = (128 * S2 + 64 * S2 + 128 + 64) * (int)sizeof(float);
    cudaFuncSetAttribute(fused_kernel, cudaFuncAttributeMaxDynamicSharedMemorySize, smem);
    fused_kernel<<<NB, NT, smem>>>(x, y, mu, nu, out);
}

// round 6
// speedup vs baseline: 2.8207x; 1.8537x over previous
#include <cuda_runtime.h>
#include <math.h>
#include <stdint.h>

#define Nn 4096
#define Mm 4096
#define LAMDA 0.01f
#define STOP_THR 1e-7
#define MAX_ITER 100
#define NB 128
#define NT 512
#define NW 16   // warps per block
#define S2 70   // smem row stride (floats)

typedef unsigned long long ull;

// ---------------- device globals (no cudaMalloc allowed) ----------------
__device__ float  g_K[(size_t)Nn * Mm];   // 64 MB kernel matrix
__device__ float  g_a[2][Nn];
__device__ float  g_b[2][Mm];
__device__ double g_bdisp[NB];
__device__ double g_bcost[NB];
__device__ unsigned g_bar_cnt;            // monotonic arrive counter (never reset)

// ---------------- fast exp: FFMA-only (no MUFU), rel err ~1e-7 ----------
__device__ __forceinline__ float fexp(float xx) {
    float t  = fmaf(xx, 1.4426950408889634f, 12582912.0f);
    int   n  = __float_as_int(t) - 0x4B400000;
    float fn = t - 12582912.0f;
    float r  = fmaf(fn, -0.693145751953125f, xx);
    r        = fmaf(fn, -1.42860677e-6f, r);
    float p  = 1.3888890e-3f;
    p = fmaf(p, r, 8.3333338e-3f);
    p = fmaf(p, r, 4.1666668e-2f);
    p = fmaf(p, r, 1.6666667e-1f);
    p = fmaf(p, r, 5.0000000e-1f);
    p = fmaf(p, r, 1.0f);
    p = fmaf(p, r, 1.0f);
    return __int_as_float(__float_as_int(p) + (n << 23));
}

#define FMA2(d, a, b) \
    asm("fma.rn.f32x2 %0, %1, %2, %0;" : "+l"(d) : "l"(a), "l"(b))
#define MUL2(d, a, b) \
    asm("mul.rn.f32x2 %0, %1, %2;" : "=l"(d) : "l"(a), "l"(b))
#define UNPACK2(lo, hi, v) \
    asm("mov.b64 {%0, %1}, %2;" : "=f"(lo), "=f"(hi) : "l"(v))

// ------------- cheap acquire/release grid barrier (no MEMBAR.GPU) -------
__device__ __forceinline__ void red_rel_add1(unsigned* p) {
    asm volatile("red.release.gpu.global.add.u32 [%0], 1;" :: "l"(p) : "memory");
}
__device__ __forceinline__ unsigned ld_acq(unsigned* p) {
    unsigned v;
    asm volatile("ld.acquire.gpu.global.u32 %0, [%1];" : "=r"(v) : "l"(p) : "memory");
    return v;
}
__device__ __forceinline__ void gbar(unsigned target) {
    __syncthreads();
    if (threadIdx.x == 0) {
        red_rel_add1(&g_bar_cnt);
        while ((int)(ld_acq(&g_bar_cnt) - target) < 0) { }
    }
    __syncthreads();
}

// ---------------- fused persistent kernel ----------------
__global__ void __launch_bounds__(NT, 1)
fused_kernel(const float* __restrict__ x, const float* __restrict__ y,
             const float* __restrict__ mu, const float* __restrict__ nu,
             float* __restrict__ out) {
    extern __shared__ float sm[];
    __shared__ float  sred[NW][33];
    __shared__ double sRow[32];
    __shared__ double sDS1[32];     // cached dan^2 * s1 per owned row
    __shared__ double sDisp;

    const int tid = threadIdx.x, blk = blockIdx.x;
    const int warp = tid >> 5, lane = tid & 31;
    const unsigned base = __ldcg(&g_bar_cnt);
    unsigned gen = 0;

    float* Pout = out + 1;                          // NOTE: 4-byte phase vs 16B — scalar only!
    float* Cmat = out + 1 + (size_t)Nn * Mm;        // same

    if (tid < 32) {
        g_a[0][blk * 32 + tid] = 1.0f / (float)Nn;
        g_b[0][blk * 32 + tid] = 1.0f;
    }

    // ================= CK phase: 16 tiles of 128x64 per block ============
    {
        float* XS = sm;                 // [128][S2]
        float* YS = sm + 128 * S2;      // [64][S2]
        float* xn = YS + 64 * S2;       // [128]
        float* yn = xn + 128;           // [64]
        const int i_tile = blk >> 2, jb = (blk & 3) * 16;
        const int i0 = i_tile * 128;

        for (int t = tid; t < 4096; t += NT) {
            int r = t >> 5, c = t & 31;
            float2 v = __ldg((const float2*)(x + (size_t)(i0 + r) * 64) + c);
            *(float2*)(XS + r * S2 + 2 * c) = v;
        }
        __syncthreads();
        if (tid < 128) {
            float s = 0.f;
            #pragma unroll
            for (int k = 0; k < 64; k++) { float v = XS[tid * S2 + k]; s = fmaf(v, v, s); }
            xn[tid] = s;
        }

        const int tx = tid & 15, ty = tid >> 4, iy = ty * 4;
        for (int s = 0; s < 16; s++) {
            const int j0 = (jb + s) * 64;
            __syncthreads();   // previous tile fully consumed
            for (int t = tid; t < 2048; t += NT) {
                int r = t >> 5, c = t & 31;
                float2 v = __ldg((const float2*)(y + (size_t)(j0 + r) * 64) + c);
                *(float2*)(YS + r * S2 + 2 * c) = v;
            }
            __syncthreads();
            if (tid < 64) {
                float sv = 0.f;
                #pragma unroll
                for (int k = 0; k < 64; k++) { float v = YS[tid * S2 + k]; sv = fmaf(v, v, sv); }
                yn[tid] = sv;
            }
            __syncthreads();

            ull acc[4][4];
            #pragma unroll
            for (int u = 0; u < 4; u++)
                #pragma unroll
                for (int w = 0; w < 4; w++) acc[u][w] = 0ULL;

            #pragma unroll 4
            for (int kp = 0; kp < 32; kp++) {
                const int k = kp * 2;
                ull xp[4], yp[4];
                #pragma unroll
                for (int u = 0; u < 4; u++)
                    xp[u] = *(const ull*)(XS + (iy + u) * S2 + k);
                #pragma unroll
                for (int w = 0; w < 4; w++)
                    yp[w] = *(const ull*)(YS + (tx + 16 * w) * S2 + k);
                #pragma unroll
                for (int u = 0; u < 4; u++)
                    #pragma unroll
                    for (int w = 0; w < 4; w++)
                        FMA2(acc[u][w], xp[u], yp[w]);
            }

            #pragma unroll
            for (int u = 0; u < 4; u++) {
                const int i = i0 + iy + u;
                const float xni = xn[iy + u];
                #pragma unroll
                for (int w = 0; w < 4; w++) {
                    const int jl = tx + 16 * w;
                    float lo, hi;
                    UNPACK2(lo, hi, acc[u][w]);
                    float Cv = xni + yn[jl] - 2.0f * (lo + hi);
                    size_t off = (size_t)i * Mm + j0 + jl;
                    __stcs(Cmat + off, Cv);
                    g_K[off] = fexp(-LAMDA * Cv);
                }
            }
        }
    }
    gbar(base + (++gen) * NB);

    // ================= Sinkhorn loop ======================================
    float* sA = sm;          // 16 KB
    float* sB = sm + Mm;     // 16 KB
    int fpar = 0;

    for (int it = 0; it < MAX_ITER; ++it) {
        const int cur = it & 1, nxt = cur ^ 1;

        // ---- Phase A: b[nxt] = nu / (K^T a[cur]); block owns cols [blk*32,+32)
        for (int i = tid; i < Nn; i += NT) sA[i] = __ldcg(&g_a[cur][i]);
        __syncthreads();
        {
            const int j = blk * 32 + lane;
            const float* Kc = g_K + j;
            float acc[8];
            #pragma unroll
            for (int u = 0; u < 8; u++) acc[u] = 0.f;
            for (int ib = 0; ib < Nn; ib += 128) {
                #pragma unroll
                for (int u = 0; u < 8; u++) {
                    const int i = ib + warp + 16 * u;
                    acc[u] = fmaf(Kc[(size_t)i * Mm], sA[i], acc[u]);
                }
            }
            float s = ((acc[0] + acc[1]) + (acc[2] + acc[3]))
                    + ((acc[4] + acc[5]) + (acc[6] + acc[7]));
            sred[warp][lane] = s;
        }
        __syncthreads();
        if (warp == 0) {
            float s = 0.f;
            #pragma unroll
            for (int w = 0; w < NW; ++w) s += sred[w][lane];
            int j = blk * 32 + lane;
            g_b[nxt][j] = __ldg(&nu[j]) / s;
        }
        gbar(base + (++gen) * NB);

        // ---- Phase B: a[nxt] = mu/(K b_new), fused f32x2 disp GEMVs
        for (int i = tid; i < Mm; i += NT) sA[i] = __ldcg(&g_b[nxt][i]);
        for (int i = tid; i < Mm; i += NT) sB[i] = __ldcg(&g_b[cur][i]);
        __syncthreads();
        #pragma unroll
        for (int rr = 0; rr < 2; ++rr) {
            const int i = blk * 32 + warp * 2 + rr;
            const ull* K2 = (const ull*)(g_K + (size_t)i * Mm);
            const ull* A2 = (const ull*)sA;
            const ull* B2 = (const ull*)sB;
            ull t = 0ULL, s1 = 0ULL, s2 = 0ULL;
            #pragma unroll 8
            for (int j = lane; j < Mm / 2; j += 32) {
                ull k = K2[j], bn = A2[j], be = B2[j];
                ull k2, tmp;
                MUL2(k2, k, k);
                FMA2(t, k, bn);
                MUL2(tmp, k2, bn);
                FMA2(s1, tmp, bn);
                FMA2(s2, tmp, be);
            }
            float tl, th, l1, h1, l2, h2;
            UNPACK2(tl, th, t);  UNPACK2(l1, h1, s1);  UNPACK2(l2, h2, s2);
            float tf = tl + th, s1f = l1 + h1, s2f = l2 + h2;
            #pragma unroll
            for (int off = 16; off; off >>= 1) {
                tf  += __shfl_down_sync(0xffffffffu, tf,  off);
                s1f += __shfl_down_sync(0xffffffffu, s1f, off);
                s2f += __shfl_down_sync(0xffffffffu, s2f, off);
            }
            if (lane == 0) {
                float an = __ldg(&mu[i]) / tf;
                g_a[nxt][i] = an;
                double dan = (double)an;
                double dao = (double)__ldcg(&g_a[cur][i]);
                double dS1 = dan * dan * (double)s1f;
                double d = (it == 0)
                    ? dS1
                    : dS1 - 2.0 * dan * dao * (double)s2f + sDS1[warp * 2 + rr];
                sDS1[warp * 2 + rr] = dS1;
                sRow[warp * 2 + rr] = d;
            }
        }
        __syncthreads();
        if (tid == 0) {
            double s = 0.0;
            #pragma unroll
            for (int q = 0; q < 32; ++q) s += sRow[q];
            g_bdisp[blk] = s;
        }
        gbar(base + (++gen) * NB);

        // ---- uniform convergence decision (warp 0 shuffle reduce)
        if (warp == 0) {
            double sd = __ldcg(&g_bdisp[lane])      + __ldcg(&g_bdisp[lane + 32])
                      + __ldcg(&g_bdisp[lane + 64]) + __ldcg(&g_bdisp[lane + 96]);
            #pragma unroll
            for (int off = 16; off; off >>= 1)
                sd += __shfl_down_sync(0xffffffffu, sd, off);
            if (lane == 0) sDisp = sd;
        }
        __syncthreads();
        fpar = nxt;
        if (sDisp <= STOP_THR) break;
    }

    // ================= epilogue: P = a*K*b^T, cost = sum(P*C) =============
    // P and C rows start at byte offset 4 (mod 16) -> K/b loads vectorized,
    // C loads / P stores SCALAR (alignment-safe).
    __syncthreads();
    for (int i = tid; i < Mm; i += NT) sA[i] = __ldcg(&g_b[fpar][i]);
    __syncthreads();

    #pragma unroll
    for (int rr = 0; rr < 2; ++rr) {
        const int i = blk * 32 + warp * 2 + rr;
        const float ai = __ldcg(&g_a[fpar][i]);
        const float4* K4 = (const float4*)(g_K + (size_t)i * Mm);
        const float4* B4 = (const float4*)sA;
        const float*  Cr = Cmat + (size_t)i * Mm;
        float*        Pr = Pout + (size_t)i * Mm;
        float cs0 = 0.f, cs1 = 0.f;
        #pragma unroll 4
        for (int q = lane; q < Mm / 4; q += 32) {
            float4 k = K4[q];
            float4 b = B4[q];
            const int j = q * 4;
            float c0 = __ldcs(Cr + j),     c1 = __ldcs(Cr + j + 1);
            float c2 = __ldcs(Cr + j + 2), c3 = __ldcs(Cr + j + 3);
            float p0 = ai * k.x * b.x, p1 = ai * k.y * b.y;
            float p2 = ai * k.z * b.z, p3 = ai * k.w * b.w;
            __stcs(Pr + j,     p0); __stcs(Pr + j + 1, p1);
            __stcs(Pr + j + 2, p2); __stcs(Pr + j + 3, p3);
            cs0 = fmaf(p0, c0, cs0); cs0 = fmaf(p1, c1, cs0);
            cs1 = fmaf(p2, c2, cs1); cs1 = fmaf(p3, c3, cs1);
        }
        float cs = cs0 + cs1;
        #pragma unroll
        for (int off = 16; off; off >>= 1)
            cs += __shfl_down_sync(0xffffffffu, cs, off);
        if (lane == 0) sRow[warp * 2 + rr] = (double)cs;
    }
    __syncthreads();
    if (tid == 0) {
        double s = 0.0;
        #pragma unroll
        for (int q = 0; q < 32; ++q) s += sRow[q];
        g_bcost[blk] = s;
    }
    gbar(base + (++gen) * NB);
    if (blk == 0 && warp == 0) {
        double sc = __ldcg(&g_bcost[lane])      + __ldcg(&g_bcost[lane + 32])
                  + __ldcg(&g_bcost[lane + 64]) + __ldcg(&g_bcost[lane + 96]);
        #pragma unroll
        for (int off = 16; off; off >>= 1)
            sc += __shfl_down_sync(0xffffffffu, sc, off);
        if (lane == 0) out[0] = (float)sc;
    }
}

// ---------------- launch ----------------
extern "C" void kernel_launch(void* const* d_in, const int* in_sizes, int n_in,
                              void* d_out, int out_size) {
    const float* x  = (const float*)d_in[0];   // [4096,64]
    const float* y  = (const float*)d_in[1];   // [4096,64]
    const float* mu = (const float*)d_in[2];   // [4096]
    const float* nu = (const float*)d_in[3];   // [4096]
    float* out = (float*)d_out;                // [1 + N*M + N*M] = cost | P | C

    const int smem = (128 * S2 + 64 * S2 + 128 + 64) * (int)sizeof(float);
    cudaFuncSetAttribute(fused_kernel, cudaFuncAttributeMaxDynamicSharedMemorySize, smem);
    fused_kernel<<<NB, NT, smem>>>(x, y, mu, nu, out);
}

// round 8
// speedup vs baseline: 3.0476x; 1.0805x over previous
#include <cuda_runtime.h>
#include <math.h>
#include <stdint.h>

#define Nn 4096
#define Mm 4096
#define LAMDA 0.01f
#define STOP_THR 1e-7
#define MAX_ITER 100
#define NB 128
#define NT 512
#define NW 16   // warps per block
#define S2 70   // smem row stride (floats) — MUST be even (8B smem accesses)

typedef unsigned long long ull;

// ---------------- device globals (no cudaMalloc allowed) ----------------
__device__ float  g_K[(size_t)Nn * Mm];   // 64 MB kernel matrix
__device__ float  g_a[2][Nn];
__device__ float  g_b[2][Mm];
__device__ double g_bdisp[NB];
__device__ double g_bcost[NB];
__device__ unsigned g_bar_cnt;            // monotonic arrive counter (never reset)

// ---------------- fast exp: FFMA-only (no MUFU), rel err ~1e-7 ----------
__device__ __forceinline__ float fexp(float xx) {
    float t  = fmaf(xx, 1.4426950408889634f, 12582912.0f);
    int   n  = __float_as_int(t) - 0x4B400000;
    float fn = t - 12582912.0f;
    float r  = fmaf(fn, -0.693145751953125f, xx);
    r        = fmaf(fn, -1.42860677e-6f, r);
    float p  = 1.3888890e-3f;
    p = fmaf(p, r, 8.3333338e-3f);
    p = fmaf(p, r, 4.1666668e-2f);
    p = fmaf(p, r, 1.6666667e-1f);
    p = fmaf(p, r, 5.0000000e-1f);
    p = fmaf(p, r, 1.0f);
    p = fmaf(p, r, 1.0f);
    return __int_as_float(__float_as_int(p) + (n << 23));
}

#define FMA2(d, a, b) \
    asm("fma.rn.f32x2 %0, %1, %2, %0;" : "+l"(d) : "l"(a), "l"(b))
#define MUL2(d, a, b) \
    asm("mul.rn.f32x2 %0, %1, %2;" : "=l"(d) : "l"(a), "l"(b))
#define UNPACK2(lo, hi, v) \
    asm("mov.b64 {%0, %1}, %2;" : "=f"(lo), "=f"(hi) : "l"(v))

// ------------- cheap acquire/release grid barrier (no MEMBAR.GPU) -------
__device__ __forceinline__ void red_rel_add1(unsigned* p) {
    asm volatile("red.release.gpu.global.add.u32 [%0], 1;" :: "l"(p) : "memory");
}
__device__ __forceinline__ unsigned ld_acq(unsigned* p) {
    unsigned v;
    asm volatile("ld.acquire.gpu.global.u32 %0, [%1];" : "=r"(v) : "l"(p) : "memory");
    return v;
}
__device__ __forceinline__ void gbar(unsigned target) {
    __syncthreads();
    if (threadIdx.x == 0) {
        red_rel_add1(&g_bar_cnt);
        while ((int)(ld_acq(&g_bar_cnt) - target) < 0) { }
    }
    __syncthreads();
}

// ---------------- fused persistent kernel ----------------
__global__ void __launch_bounds__(NT, 1)
fused_kernel(const float* __restrict__ x, const float* __restrict__ y,
             const float* __restrict__ mu, const float* __restrict__ nu,
             float* __restrict__ out) {
    extern __shared__ float sm[];
    __shared__ float  sred[NW][33];
    __shared__ double sRow[32];
    __shared__ double sDS1[32];
    __shared__ double sDisp;

    const int tid = threadIdx.x, blk = blockIdx.x;
    const int warp = tid >> 5, lane = tid & 31;
    const unsigned FULL = 0xffffffffu;
    const unsigned base = __ldcg(&g_bar_cnt);
    unsigned gen = 0;

    float* Pout = out + 1;                    // rows at byte phase 4 (mod 16)
    float* Cmat = out + 1 + (size_t)Nn * Mm;  // same phase

    if (tid < 32) {
        g_a[0][blk * 32 + tid] = 1.0f / (float)Nn;
        g_b[0][blk * 32 + tid] = 1.0f;
    }

    // ================= CK phase: 16 tiles of 128x64 per block ============
    // Only K = exp(-lamda*C) is stored.  C reconstructed later as -100*ln(K).
    {
        float* XS = sm;                 // [128][S2]
        float* YS = sm + 128 * S2;      // [64][S2]
        float* xn = YS + 64 * S2;       // [128]
        float* yn = xn + 128;           // [64]
        const int i_tile = blk >> 2, jb = (blk & 3) * 16;
        const int i0 = i_tile * 128;

        for (int t = tid; t < 4096; t += NT) {
            int r = t >> 5, c = t & 31;
            float2 v = __ldg((const float2*)(x + (size_t)(i0 + r) * 64) + c);
            *(float2*)(XS + r * S2 + 2 * c) = v;
        }
        __syncthreads();
        if (tid < 128) {
            float s = 0.f;
            #pragma unroll
            for (int k = 0; k < 64; k++) { float v = XS[tid * S2 + k]; s = fmaf(v, v, s); }
            xn[tid] = s;
        }

        const int tx = tid & 15, ty = tid >> 4, iy = ty * 4;
        for (int s = 0; s < 16; s++) {
            const int j0 = (jb + s) * 64;
            __syncthreads();   // previous tile fully consumed
            for (int t = tid; t < 2048; t += NT) {
                int r = t >> 5, c = t & 31;
                float2 v = __ldg((const float2*)(y + (size_t)(j0 + r) * 64) + c);
                *(float2*)(YS + r * S2 + 2 * c) = v;
            }
            __syncthreads();
            if (tid < 64) {
                float sv = 0.f;
                #pragma unroll
                for (int k = 0; k < 64; k++) { float v = YS[tid * S2 + k]; sv = fmaf(v, v, sv); }
                yn[tid] = sv;
            }
            __syncthreads();

            ull acc[4][4];
            #pragma unroll
            for (int u = 0; u < 4; u++)
                #pragma unroll
                for (int w = 0; w < 4; w++) acc[u][w] = 0ULL;

            #pragma unroll 4
            for (int kp = 0; kp < 32; kp++) {
                const int k = kp * 2;
                ull xp[4], yp[4];
                #pragma unroll
                for (int u = 0; u < 4; u++)
                    xp[u] = *(const ull*)(XS + (iy + u) * S2 + k);
                #pragma unroll
                for (int w = 0; w < 4; w++)
                    yp[w] = *(const ull*)(YS + (tx + 16 * w) * S2 + k);
                #pragma unroll
                for (int u = 0; u < 4; u++)
                    #pragma unroll
                    for (int w = 0; w < 4; w++)
                        FMA2(acc[u][w], xp[u], yp[w]);
            }

            #pragma unroll
            for (int u = 0; u < 4; u++) {
                const int i = i0 + iy + u;
                const float xni = xn[iy + u];
                #pragma unroll
                for (int w = 0; w < 4; w++) {
                    const int jl = tx + 16 * w;
                    float lo, hi;
                    UNPACK2(lo, hi, acc[u][w]);
                    float Cv = xni + yn[jl] - 2.0f * (lo + hi);
                    g_K[(size_t)i * Mm + j0 + jl] = fexp(-LAMDA * Cv);
                }
            }
        }
    }
    gbar(base + (++gen) * NB);

    // ================= Sinkhorn loop ======================================
    float* sA = sm;          // 16 KB
    float* sB = sm + Mm;     // 16 KB
    int fpar = 0;

    for (int it = 0; it < MAX_ITER; ++it) {
        const int cur = it & 1, nxt = cur ^ 1;

        // ---- Phase A: b[nxt] = nu / (K^T a[cur]); block owns cols [blk*32,+32)
        for (int i = tid; i < Nn; i += NT) sA[i] = __ldcg(&g_a[cur][i]);
        __syncthreads();
        {
            const int j = blk * 32 + lane;
            const float* Kc = g_K + j;
            float acc[8];
            #pragma unroll
            for (int u = 0; u < 8; u++) acc[u] = 0.f;
            for (int ib = 0; ib < Nn; ib += 128) {
                #pragma unroll
                for (int u = 0; u < 8; u++) {
                    const int i = ib + warp + 16 * u;
                    acc[u] = fmaf(Kc[(size_t)i * Mm], sA[i], acc[u]);
                }
            }
            float s = ((acc[0] + acc[1]) + (acc[2] + acc[3]))
                    + ((acc[4] + acc[5]) + (acc[6] + acc[7]));
            sred[warp][lane] = s;
        }
        __syncthreads();
        if (warp == 0) {
            float s = 0.f;
            #pragma unroll
            for (int w = 0; w < NW; ++w) s += sred[w][lane];
            int j = blk * 32 + lane;
            g_b[nxt][j] = __ldg(&nu[j]) / s;
        }
        gbar(base + (++gen) * NB);

        // ---- Phase B: a[nxt] = mu/(K b_new), fused f32x2 disp GEMVs
        for (int i = tid; i < Mm; i += NT) sA[i] = __ldcg(&g_b[nxt][i]);
        for (int i = tid; i < Mm; i += NT) sB[i] = __ldcg(&g_b[cur][i]);
        __syncthreads();
        #pragma unroll
        for (int rr = 0; rr < 2; ++rr) {
            const int i = blk * 32 + warp * 2 + rr;
            const ull* K2 = (const ull*)(g_K + (size_t)i * Mm);
            const ull* A2 = (const ull*)sA;
            const ull* B2 = (const ull*)sB;
            ull t = 0ULL, s1 = 0ULL, s2 = 0ULL;
            #pragma unroll 8
            for (int j = lane; j < Mm / 2; j += 32) {
                ull k = K2[j], bn = A2[j], be = B2[j];
                ull k2, tmp;
                MUL2(k2, k, k);
                FMA2(t, k, bn);
                MUL2(tmp, k2, bn);
                FMA2(s1, tmp, bn);
                FMA2(s2, tmp, be);
            }
            float tl, th, l1, h1, l2, h2;
            UNPACK2(tl, th, t);  UNPACK2(l1, h1, s1);  UNPACK2(l2, h2, s2);
            float tf = tl + th, s1f = l1 + h1, s2f = l2 + h2;
            #pragma unroll
            for (int off = 16; off; off >>= 1) {
                tf  += __shfl_down_sync(FULL, tf,  off);
                s1f += __shfl_down_sync(FULL, s1f, off);
                s2f += __shfl_down_sync(FULL, s2f, off);
            }
            if (lane == 0) {
                float an = __ldg(&mu[i]) / tf;
                g_a[nxt][i] = an;
                double dan = (double)an;
                double dao = (double)__ldcg(&g_a[cur][i]);
                double dS1 = dan * dan * (double)s1f;
                double d = (it == 0)
                    ? dS1
                    : dS1 - 2.0 * dan * dao * (double)s2f + sDS1[warp * 2 + rr];
                sDS1[warp * 2 + rr] = dS1;
                sRow[warp * 2 + rr] = d;
            }
        }
        __syncthreads();
        if (tid == 0) {
            double s = 0.0;
            #pragma unroll
            for (int q = 0; q < 32; ++q) s += sRow[q];
            g_bdisp[blk] = s;
        }
        gbar(base + (++gen) * NB);

        if (warp == 0) {
            double sd = __ldcg(&g_bdisp[lane])      + __ldcg(&g_bdisp[lane + 32])
                      + __ldcg(&g_bdisp[lane + 64]) + __ldcg(&g_bdisp[lane + 96]);
            #pragma unroll
            for (int off = 16; off; off >>= 1)
                sd += __shfl_down_sync(FULL, sd, off);
            if (lane == 0) sDisp = sd;
        }
        __syncthreads();
        fpar = nxt;
        if (sDisp <= STOP_THR) break;
    }

    // ================= epilogue: P = a*K*b^T, C = -100*ln(K), cost ========
    // P/C rows are at byte phase 4 (mod 16): aligned quads start at j=3+4q.
    // K quads from aligned LDG.128 + lane-shuffle window; b pre-shifted in smem.
    __syncthreads();
    for (int i = tid; i < Mm; i += NT) sA[i] = __ldcg(&g_b[fpar][i]);
    __syncthreads();
    for (int m = tid; m < Mm - 3; m += NT) sB[m] = sA[m + 3];   // shifted copy
    __syncthreads();
    const float4* Bsh4 = (const float4*)sB;

    #pragma unroll
    for (int rr = 0; rr < 2; ++rr) {
        const int i = blk * 32 + warp * 2 + rr;
        const float ai = __ldcg(&g_a[fpar][i]);
        const float*  Kr = g_K + (size_t)i * Mm;
        const float4* K4 = (const float4*)Kr;
        float* Pr = Pout + (size_t)i * Mm;
        float* Cr = Cmat + (size_t)i * Mm;
        float csum = 0.f;

        // head: j = 0,1,2
        if (lane < 3) {
            float k = Kr[lane];
            float p = ai * k * sA[lane];
            float c = -69.31471805599453f * __log2f(k);
            __stcs(Pr + lane, p);
            __stcs(Cr + lane, c);
            csum = fmaf(p, c, csum);
        }

        float4 curr = K4[lane];           // quad q = lane
        for (int s = 0; s < 32; s++) {
            const int q = lane + 32 * s;
            const int nidx = (s < 31) ? (lane + 32 * (s + 1)) : lane;  // dummy at s=31
            float4 newq = K4[nidx];
            float nx = __shfl_down_sync(FULL, curr.x, 1);
            float ny = __shfl_down_sync(FULL, curr.y, 1);
            float nz = __shfl_down_sync(FULL, curr.z, 1);
            float bx = __shfl_sync(FULL, newq.x, 0);
            float by = __shfl_sync(FULL, newq.y, 0);
            float bz = __shfl_sync(FULL, newq.z, 0);
            if (lane == 31) { nx = bx; ny = by; nz = bz; }

            if (q <= 1022) {
                const int jst = 4 * q + 3;
                float k0 = curr.w, k1 = nx, k2 = ny, k3 = nz;
                float4 bq = Bsh4[q];                  // b[jst..jst+3]
                float p0 = ai * k0 * bq.x, p1 = ai * k1 * bq.y;
                float p2 = ai * k2 * bq.z, p3 = ai * k3 * bq.w;
                float c0 = -69.31471805599453f * __log2f(k0);
                float c1 = -69.31471805599453f * __log2f(k1);
                float c2 = -69.31471805599453f * __log2f(k2);
                float c3 = -69.31471805599453f * __log2f(k3);
                float4 pq; pq.x = p0; pq.y = p1; pq.z = p2; pq.w = p3;
                float4 cq; cq.x = c0; cq.y = c1; cq.z = c2; cq.w = c3;
                __stcs((float4*)(Pr + jst), pq);
                __stcs((float4*)(Cr + jst), cq);
                csum = fmaf(p0, c0, csum); csum = fmaf(p1, c1, csum);
                csum = fmaf(p2, c2, csum); csum = fmaf(p3, c3, csum);
            }
            if (s == 31 && lane == 31) {              // tail j = 4095
                float k = curr.w;
                float p = ai * k * sA[4095];
                float c = -69.31471805599453f * __log2f(k);
                __stcs(Pr + 4095, p);
                __stcs(Cr + 4095, c);
                csum = fmaf(p, c, csum);
            }
            curr = newq;
        }

        #pragma unroll
        for (int off = 16; off; off >>= 1)
            csum += __shfl_down_sync(FULL, csum, off);
        if (lane == 0) sRow[warp * 2 + rr] = (double)csum;
    }
    __syncthreads();
    if (tid == 0) {
        double s = 0.0;
        #pragma unroll
        for (int q = 0; q < 32; ++q) s += sRow[q];
        g_bcost[blk] = s;
    }
    gbar(base + (++gen) * NB);
    if (blk == 0 && warp == 0) {
        double sc = __ldcg(&g_bcost[lane])      + __ldcg(&g_bcost[lane + 32])
                  + __ldcg(&g_bcost[lane + 64]) + __ldcg(&g_bcost[lane + 96]);
        #pragma unroll
        for (int off = 16; off; off >>= 1)
            sc += __shfl_down_sync(FULL, sc, off);
        if (lane == 0) out[0] = (float)sc;
    }
}

// ---------------- launch ----------------
extern "C" void kernel_launch(void* const* d_in, const int* in_sizes, int n_in,
                              void* d_out, int out_size) {
    const float* x  = (const float*)d_in[0];   // [4096,64]
    const float* y  = (const float*)d_in[1];   // [4096,64]
    const float* mu = (const float*)d_in[2];   // [4096]
    const float* nu = (const float*)d_in[3];   // [4096]
    float* out = (float*)d_out;                // [1 + N*M + N*M] = cost | P | C

    const int smem = (128 * S2 + 64 * S2 + 128 + 64) * (int)sizeof(float);
    cudaFuncSetAttribute(fused_kernel, cudaFuncAttributeMaxDynamicSharedMemorySize, smem);
    fused_kernel<<<NB, NT, smem>>>(x, y, mu, nu, out);
}